// round 5
// baseline (speedup 1.0000x reference)
#include <cuda_runtime.h>
#include <cuda_fp16.h>
#include <cstdint>

#define NUSER 50000
#define NITEM 50000
#define NEDGE 1600000
#define D 64

// ---- Scratch (device globals; allocation is forbidden) ----
__device__ int g_deg_item[NITEM];
__device__ int g_deg_user[NUSER];
__device__ int g_off_item[NITEM];
__device__ int g_off_user[NUSER];
__device__ int g_cur_item[NITEM];
__device__ int g_cur_user[NUSER];
__device__ int g_esrc_item[NEDGE];        // user ids, grouped by dst item
__device__ int g_esrc_user[NEDGE];        // item ids, grouped by dst user
__device__ __half g_uf_h[NUSER * D];      // user_feat in fp16 (gather table)
__device__ __half g_if_h[NITEM * D];      // item_feat in fp16 (gather table)
__device__ float g_mean_item[NITEM * D];  // mean of user_feat over in-edges
__device__ float g_mean_user[NUSER * D];  // mean of item_feat over in-edges

// ---------------------------------------------------------------------------
// Zero the degree counters.
// ---------------------------------------------------------------------------
__global__ void init_kernel() {
    int i = blockIdx.x * blockDim.x + threadIdx.x;
    if (i < NITEM) g_deg_item[i] = 0;
    if (i < NUSER) g_deg_user[i] = 0;
}

// ---------------------------------------------------------------------------
// Convert both fp32 feature tables to fp16 gather tables (float4 -> 4 halves).
// ---------------------------------------------------------------------------
__global__ void conv_kernel(const float* __restrict__ user_feat,
                            const float* __restrict__ item_feat) {
    const int n4 = NUSER * D / 4;          // 800000 per side
    int i = blockIdx.x * blockDim.x + threadIdx.x;
    if (i < n4) {
        float4 v = *reinterpret_cast<const float4*>(user_feat + (size_t)i * 4);
        __half2 lo = __floats2half2_rn(v.x, v.y);
        __half2 hi = __floats2half2_rn(v.z, v.w);
        uint2 p = make_uint2(*reinterpret_cast<uint32_t*>(&lo),
                             *reinterpret_cast<uint32_t*>(&hi));
        *reinterpret_cast<uint2*>(g_uf_h + (size_t)i * 4) = p;
    } else if (i < 2 * n4) {
        int j = i - n4;
        float4 v = *reinterpret_cast<const float4*>(item_feat + (size_t)j * 4);
        __half2 lo = __floats2half2_rn(v.x, v.y);
        __half2 hi = __floats2half2_rn(v.z, v.w);
        uint2 p = make_uint2(*reinterpret_cast<uint32_t*>(&lo),
                             *reinterpret_cast<uint32_t*>(&hi));
        *reinterpret_cast<uint2*>(g_if_h + (size_t)j * 4) = p;
    }
}

// ---------------------------------------------------------------------------
// Degree histogram for both edge types (int atomics, spread addresses).
// ---------------------------------------------------------------------------
__global__ void hist_kernel(const int* __restrict__ rate_dst,
                            const int* __restrict__ rev_dst) {
    int i = blockIdx.x * blockDim.x + threadIdx.x;
    if (i < NEDGE) {
        atomicAdd(&g_deg_item[__ldg(rate_dst + i)], 1);
        atomicAdd(&g_deg_user[__ldg(rev_dst + i)], 1);
    }
}

// ---------------------------------------------------------------------------
// Exclusive prefix sum over the 50K degree bins (2 blocks: item / user).
// Chunked: each thread owns 49 contiguous elements. Pass 1 sums the chunk,
// one block-level scan of 1024 chunk sums (2 barriers), pass 2 writes
// running offsets. Data is L2-resident; critical path ~ 2 barriers.
// ---------------------------------------------------------------------------
__global__ void scan_kernel() {
    const int n = (blockIdx.x == 0) ? NITEM : NUSER;
    const int* __restrict__ deg = (blockIdx.x == 0) ? g_deg_item : g_deg_user;
    int* __restrict__ off = (blockIdx.x == 0) ? g_off_item : g_off_user;
    int* __restrict__ cur = (blockIdx.x == 0) ? g_cur_item : g_cur_user;

    const int CH = (n + 1023) / 1024;      // 49
    const int tid = threadIdx.x, lane = tid & 31, wid = tid >> 5;
    const int base = tid * CH;
    const int lim = min(base + CH, n);

    // Pass 1: chunk sum.
    int s = 0;
    for (int i = base; i < lim; i++) s += __ldg(deg + i);

    // Block-level exclusive scan of the 1024 chunk sums.
    __shared__ int wsum[32];
    int p = s;
    #pragma unroll
    for (int o = 1; o < 32; o <<= 1) {
        int t = __shfl_up_sync(0xffffffffu, p, o);
        if (lane >= o) p += t;
    }
    if (lane == 31) wsum[wid] = p;
    __syncthreads();
    if (wid == 0) {
        int ws = wsum[lane];
        #pragma unroll
        for (int o = 1; o < 32; o <<= 1) {
            int t = __shfl_up_sync(0xffffffffu, ws, o);
            if (lane >= o) ws += t;
        }
        wsum[lane] = ws;
    }
    __syncthreads();
    int running = (wid ? wsum[wid - 1] : 0) + p - s;   // exclusive chunk offset

    // Pass 2: write running exclusive offsets (deg re-read hits L1/L2).
    for (int i = base; i < lim; i++) {
        off[i] = running;
        cur[i] = running;
        running += __ldg(deg + i);
    }
}

// ---------------------------------------------------------------------------
// Bin edges by destination: slot = atomic cursor bump, store source id.
// ---------------------------------------------------------------------------
__global__ void bin_kernel(const int* __restrict__ rate_src, const int* __restrict__ rate_dst,
                           const int* __restrict__ rev_src,  const int* __restrict__ rev_dst) {
    int i = blockIdx.x * blockDim.x + threadIdx.x;
    if (i < NEDGE) {
        int p = atomicAdd(&g_cur_item[__ldg(rate_dst + i)], 1);
        g_esrc_item[p] = __ldg(rate_src + i);
        int q = atomicAdd(&g_cur_user[__ldg(rev_dst + i)], 1);
        g_esrc_user[q] = __ldg(rev_src + i);
    }
}

// ---------------------------------------------------------------------------
// Gather-based segment mean over fp16 rows: 16 threads per dst node, each
// owns 4 halves (8B) of the 128B row. Accumulate fp32, write fp32 mean.
// ---------------------------------------------------------------------------
__global__ void agg_kernel(const __half* __restrict__ feat, const int* __restrict__ esrc,
                           const int* __restrict__ off, const int* __restrict__ deg,
                           float* __restrict__ mean) {
    int t = blockIdx.x * blockDim.x + threadIdx.x;
    int g = t >> 4;          // node id (grid sized exactly: nnode*16 threads)
    int lane = t & 15;
    int dgc = __ldg(deg + g);
    int start = __ldg(off + g);
    float4 acc = make_float4(0.f, 0.f, 0.f, 0.f);
    #pragma unroll 4
    for (int j = 0; j < dgc; j++) {
        int s = __ldg(esrc + start + j);
        uint2 p = *reinterpret_cast<const uint2*>(feat + (size_t)s * D + lane * 4);
        __half2 h0 = *reinterpret_cast<__half2*>(&p.x);
        __half2 h1 = *reinterpret_cast<__half2*>(&p.y);
        float2 f0 = __half22float2(h0);
        float2 f1 = __half22float2(h1);
        acc.x += f0.x; acc.y += f0.y; acc.z += f1.x; acc.w += f1.y;
    }
    float inv = (dgc > 0) ? 1.f / (float)dgc : 0.f;
    acc.x *= inv; acc.y *= inv; acc.z *= inv; acc.w *= inv;
    *reinterpret_cast<float4*>(mean + (size_t)g * D + lane * 4) = acc;
}

// ---------------------------------------------------------------------------
// Fused dual GEMM finalize:
//   out = feat @ W_loop + mean @ W_et + (deg>0 ? b_et : 0) + h_bias
// 64-row tile, 4x4 register blocking, two accumulate phases over shared tiles.
// ---------------------------------------------------------------------------
__global__ void final_kernel(const float* __restrict__ A0, const float* __restrict__ W0,
                             const float* __restrict__ A1, const float* __restrict__ W1,
                             const float* __restrict__ bet, const float* __restrict__ hb,
                             const int* __restrict__ deg, float* __restrict__ out, int N) {
    __shared__ float As[64][68];
    __shared__ float Ws[64][68];
    __shared__ float bias_h[64];
    __shared__ float bias_e[64];
    const int tid = threadIdx.x;
    const int tx = tid & 15, ty = tid >> 4;
    const int row0 = blockIdx.x * 64;
    const int rb = ty * 4;

    if (tid < 64) bias_h[tid] = hb[tid];
    else if (tid < 128) bias_e[tid - 64] = bet[tid - 64];

    float4 acc[4];
    #pragma unroll
    for (int i = 0; i < 4; i++) acc[i] = make_float4(0.f, 0.f, 0.f, 0.f);

    #pragma unroll
    for (int phase = 0; phase < 2; phase++) {
        const float* A = phase ? A1 : A0;
        const float* W = phase ? W1 : W0;
        __syncthreads();   // protect shared reuse from previous phase
        #pragma unroll
        for (int i = tid; i < 1024; i += 256) {
            int k = i >> 4, c4 = (i & 15) << 2;
            float4 w = *reinterpret_cast<const float4*>(W + k * 64 + c4);
            *reinterpret_cast<float4*>(&Ws[k][c4]) = w;
        }
        #pragma unroll
        for (int i = tid; i < 1024; i += 256) {
            int r = i >> 4, k4 = (i & 15) << 2;
            int gr = row0 + r;
            float4 a = (gr < N) ? *reinterpret_cast<const float4*>(A + (size_t)gr * D + k4)
                                : make_float4(0.f, 0.f, 0.f, 0.f);
            *reinterpret_cast<float4*>(&As[r][k4]) = a;
        }
        __syncthreads();
        #pragma unroll
        for (int k = 0; k < 64; k++) {
            float4 wv = *reinterpret_cast<const float4*>(&Ws[k][tx * 4]);
            float a0 = As[rb + 0][k], a1 = As[rb + 1][k], a2 = As[rb + 2][k], a3 = As[rb + 3][k];
            acc[0].x += a0 * wv.x; acc[0].y += a0 * wv.y; acc[0].z += a0 * wv.z; acc[0].w += a0 * wv.w;
            acc[1].x += a1 * wv.x; acc[1].y += a1 * wv.y; acc[1].z += a1 * wv.z; acc[1].w += a1 * wv.w;
            acc[2].x += a2 * wv.x; acc[2].y += a2 * wv.y; acc[2].z += a2 * wv.z; acc[2].w += a2 * wv.w;
            acc[3].x += a3 * wv.x; acc[3].y += a3 * wv.y; acc[3].z += a3 * wv.z; acc[3].w += a3 * wv.w;
        }
    }

    #pragma unroll
    for (int i = 0; i < 4; i++) {
        int gr = row0 + rb + i;
        if (gr < N) {
            float m = (__ldg(deg + gr) > 0) ? 1.f : 0.f;
            float4 r = acc[i];
            r.x += bias_h[tx * 4 + 0] + m * bias_e[tx * 4 + 0];
            r.y += bias_h[tx * 4 + 1] + m * bias_e[tx * 4 + 1];
            r.z += bias_h[tx * 4 + 2] + m * bias_e[tx * 4 + 2];
            r.w += bias_h[tx * 4 + 3] + m * bias_e[tx * 4 + 3];
            *reinterpret_cast<float4*>(out + (size_t)gr * D + tx * 4) = r;
        }
    }
}

extern "C" void kernel_launch(void* const* d_in, const int* in_sizes, int n_in,
                              void* d_out, int out_size) {
    const float* user_feat = (const float*)d_in[0];
    const float* item_feat = (const float*)d_in[1];
    const int*   rate_src  = (const int*)d_in[2];
    const int*   rate_dst  = (const int*)d_in[3];
    const int*   rev_src   = (const int*)d_in[4];
    const int*   rev_dst   = (const int*)d_in[5];
    const float* W_rate    = (const float*)d_in[6];
    const float* b_rate    = (const float*)d_in[7];
    const float* W_rev     = (const float*)d_in[8];
    const float* b_rev     = (const float*)d_in[9];
    const float* W_loop    = (const float*)d_in[10];
    const float* h_bias    = (const float*)d_in[11];

    float* out      = (float*)d_out;
    float* out_user = out;
    float* out_item = out + (size_t)NUSER * D;

    int *deg_item, *deg_user, *esrc_item, *esrc_user, *off_item, *off_user;
    float *mean_item, *mean_user;
    __half *uf_h, *if_h;
    cudaGetSymbolAddress((void**)&deg_item, g_deg_item);
    cudaGetSymbolAddress((void**)&deg_user, g_deg_user);
    cudaGetSymbolAddress((void**)&off_item, g_off_item);
    cudaGetSymbolAddress((void**)&off_user, g_off_user);
    cudaGetSymbolAddress((void**)&esrc_item, g_esrc_item);
    cudaGetSymbolAddress((void**)&esrc_user, g_esrc_user);
    cudaGetSymbolAddress((void**)&mean_item, g_mean_item);
    cudaGetSymbolAddress((void**)&mean_user, g_mean_user);
    cudaGetSymbolAddress((void**)&uf_h, g_uf_h);
    cudaGetSymbolAddress((void**)&if_h, g_if_h);

    init_kernel<<<(NUSER + 255) / 256, 256>>>();
    conv_kernel<<<(2 * NUSER * D / 4 + 255) / 256, 256>>>(user_feat, item_feat);
    hist_kernel<<<(NEDGE + 255) / 256, 256>>>(rate_dst, rev_dst);
    scan_kernel<<<2, 1024>>>();
    bin_kernel<<<(NEDGE + 255) / 256, 256>>>(rate_src, rate_dst, rev_src, rev_dst);

    // item side aggregates USER features; user side aggregates ITEM features.
    agg_kernel<<<NITEM * 16 / 256, 256>>>(uf_h, esrc_item, off_item, deg_item, mean_item);
    agg_kernel<<<NUSER * 16 / 256, 256>>>(if_h, esrc_user, off_user, deg_user, mean_user);

    final_kernel<<<(NUSER + 63) / 64, 256>>>(user_feat, W_loop, mean_user, W_rev,
                                             b_rev, h_bias, deg_user, out_user, NUSER);
    final_kernel<<<(NITEM + 63) / 64, 256>>>(item_feat, W_loop, mean_item, W_rate,
                                             b_rate, h_bias, deg_item, out_item, NITEM);
}

// round 6
// speedup vs baseline: 1.3461x; 1.3461x over previous
#include <cuda_runtime.h>
#include <cuda_fp16.h>
#include <cstdint>

#define NUSER 50000
#define NITEM 50000
#define NEDGE 1600000
#define D 64

#define TILE 1024
#define NTILE ((NUSER + TILE - 1) / TILE)   // 49 tiles per side

// ---- Scratch (device globals; allocation is forbidden) ----
__device__ __align__(16) int g_deg_item[NITEM];
__device__ __align__(16) int g_deg_user[NUSER];
__device__ __align__(16) int g_off_item[NITEM];
__device__ __align__(16) int g_off_user[NUSER];
__device__ __align__(16) int g_cur_item[NITEM];
__device__ __align__(16) int g_cur_user[NUSER];
__device__ int g_tsum[2][NTILE];          // per-tile sums (0=item, 1=user)
__device__ int g_tbase[2][NTILE];         // exclusive tile bases
__device__ int g_esrc_item[NEDGE];        // user ids, grouped by dst item
__device__ int g_esrc_user[NEDGE];        // item ids, grouped by dst user
__device__ __half g_uf_h[NUSER * D];      // user_feat in fp16 (gather table)
__device__ __half g_if_h[NITEM * D];      // item_feat in fp16 (gather table)
__device__ float g_mean_item[NITEM * D];  // mean of user_feat over in-edges
__device__ float g_mean_user[NUSER * D];  // mean of item_feat over in-edges

// ---------------------------------------------------------------------------
// Zero the degree counters.
// ---------------------------------------------------------------------------
__global__ void init_kernel() {
    int i = blockIdx.x * blockDim.x + threadIdx.x;
    if (i < NITEM) g_deg_item[i] = 0;
    if (i < NUSER) g_deg_user[i] = 0;
}

// ---------------------------------------------------------------------------
// Convert both fp32 feature tables to fp16 gather tables (float4 -> 4 halves).
// ---------------------------------------------------------------------------
__global__ void conv_kernel(const float* __restrict__ user_feat,
                            const float* __restrict__ item_feat) {
    const int n4 = NUSER * D / 4;          // 800000 per side
    int i = blockIdx.x * blockDim.x + threadIdx.x;
    if (i < n4) {
        float4 v = *reinterpret_cast<const float4*>(user_feat + (size_t)i * 4);
        __half2 lo = __floats2half2_rn(v.x, v.y);
        __half2 hi = __floats2half2_rn(v.z, v.w);
        uint2 p = make_uint2(*reinterpret_cast<uint32_t*>(&lo),
                             *reinterpret_cast<uint32_t*>(&hi));
        *reinterpret_cast<uint2*>(g_uf_h + (size_t)i * 4) = p;
    } else if (i < 2 * n4) {
        int j = i - n4;
        float4 v = *reinterpret_cast<const float4*>(item_feat + (size_t)j * 4);
        __half2 lo = __floats2half2_rn(v.x, v.y);
        __half2 hi = __floats2half2_rn(v.z, v.w);
        uint2 p = make_uint2(*reinterpret_cast<uint32_t*>(&lo),
                             *reinterpret_cast<uint32_t*>(&hi));
        *reinterpret_cast<uint2*>(g_if_h + (size_t)j * 4) = p;
    }
}

// ---------------------------------------------------------------------------
// Degree histogram for both edge types (int atomics, spread addresses).
// ---------------------------------------------------------------------------
__global__ void hist_kernel(const int* __restrict__ rate_dst,
                            const int* __restrict__ rev_dst) {
    int i = blockIdx.x * blockDim.x + threadIdx.x;
    if (i < NEDGE) {
        atomicAdd(&g_deg_item[__ldg(rate_dst + i)], 1);
        atomicAdd(&g_deg_user[__ldg(rev_dst + i)], 1);
    }
}

// ---------------------------------------------------------------------------
// Scan step 1: per-tile reduction. Grid = 2*NTILE blocks, 256 threads.
// Block b: side = b / NTILE, tile = b % NTILE. Coalesced int4 loads.
// ---------------------------------------------------------------------------
__global__ void scan1_kernel() {
    int side = blockIdx.x / NTILE;
    int tile = blockIdx.x % NTILE;
    const int n = (side == 0) ? NITEM : NUSER;
    const int* __restrict__ deg = (side == 0) ? g_deg_item : g_deg_user;
    const int tid = threadIdx.x;
    const int e0 = tile * TILE + tid * 4;

    int s = 0;
    if (e0 + 3 < n) {
        int4 v = *reinterpret_cast<const int4*>(deg + e0);
        s = v.x + v.y + v.z + v.w;
    } else {
        for (int i = e0; i < min(e0 + 4, n); i++) s += __ldg(deg + i);
    }
    // warp reduce + block reduce
    #pragma unroll
    for (int o = 16; o; o >>= 1) s += __shfl_down_sync(0xffffffffu, s, o);
    __shared__ int ws[8];
    if ((tid & 31) == 0) ws[tid >> 5] = s;
    __syncthreads();
    if (tid < 8) {
        int t = ws[tid];
        #pragma unroll
        for (int o = 4; o; o >>= 1) t += __shfl_down_sync(0xffu, t, o);
        if (tid == 0) g_tsum[side][tile] = t;
    }
}

// ---------------------------------------------------------------------------
// Scan step 2: exclusive scan of the NTILE (49) tile sums, one warp per side.
// ---------------------------------------------------------------------------
__global__ void scan2_kernel() {
    int side = threadIdx.x >> 5;     // 2 warps
    int lane = threadIdx.x & 31;
    if (side < 2) {
        int v0 = (lane < NTILE) ? g_tsum[side][lane] : 0;
        int v1 = (lane + 32 < NTILE) ? g_tsum[side][lane + 32] : 0;
        int s0 = v0, s1 = v1;
        #pragma unroll
        for (int o = 1; o < 32; o <<= 1) {
            int t = __shfl_up_sync(0xffffffffu, s0, o);
            if (lane >= o) s0 += t;
            int u = __shfl_up_sync(0xffffffffu, s1, o);
            if (lane >= o) s1 += u;
        }
        int tot0 = __shfl_sync(0xffffffffu, s0, 31);
        if (lane < NTILE) g_tbase[side][lane] = s0 - v0;
        if (lane + 32 < NTILE) g_tbase[side][lane + 32] = tot0 + s1 - v1;
    }
}

// ---------------------------------------------------------------------------
// Scan step 3: per-tile exclusive scan + tile base -> off/cur. Coalesced.
// Each thread owns 4 consecutive elements (int4 in/out), block-scan of
// thread sums (2 barriers).
// ---------------------------------------------------------------------------
__global__ void scan3_kernel() {
    int side = blockIdx.x / NTILE;
    int tile = blockIdx.x % NTILE;
    const int n = (side == 0) ? NITEM : NUSER;
    const int* __restrict__ deg = (side == 0) ? g_deg_item : g_deg_user;
    int* __restrict__ off = (side == 0) ? g_off_item : g_off_user;
    int* __restrict__ cur = (side == 0) ? g_cur_item : g_cur_user;
    const int tid = threadIdx.x, lane = tid & 31, wid = tid >> 5;
    const int e0 = tile * TILE + tid * 4;

    int4 v = make_int4(0, 0, 0, 0);
    if (e0 + 3 < n) {
        v = *reinterpret_cast<const int4*>(deg + e0);
    } else {
        if (e0 + 0 < n) v.x = __ldg(deg + e0 + 0);
        if (e0 + 1 < n) v.y = __ldg(deg + e0 + 1);
        if (e0 + 2 < n) v.z = __ldg(deg + e0 + 2);
        if (e0 + 3 < n) v.w = __ldg(deg + e0 + 3);
    }
    int tsum = v.x + v.y + v.z + v.w;

    // block exclusive scan of 256 thread sums
    int p = tsum;
    #pragma unroll
    for (int o = 1; o < 32; o <<= 1) {
        int t = __shfl_up_sync(0xffffffffu, p, o);
        if (lane >= o) p += t;
    }
    __shared__ int ws[8];
    if (lane == 31) ws[wid] = p;
    __syncthreads();
    if (tid < 8) {
        int t = ws[tid];
        #pragma unroll
        for (int o = 1; o < 8; o <<= 1) {
            int u = __shfl_up_sync(0xffu, t, o);
            if (tid >= o) t += u;
        }
        ws[tid] = t;
    }
    __syncthreads();
    int excl = (wid ? ws[wid - 1] : 0) + p - tsum + g_tbase[side][tile];

    int4 o4;
    o4.x = excl;
    o4.y = o4.x + v.x;
    o4.z = o4.y + v.y;
    o4.w = o4.z + v.z;
    if (e0 + 3 < n) {
        *reinterpret_cast<int4*>(off + e0) = o4;
        *reinterpret_cast<int4*>(cur + e0) = o4;
    } else {
        if (e0 + 0 < n) { off[e0 + 0] = o4.x; cur[e0 + 0] = o4.x; }
        if (e0 + 1 < n) { off[e0 + 1] = o4.y; cur[e0 + 1] = o4.y; }
        if (e0 + 2 < n) { off[e0 + 2] = o4.z; cur[e0 + 2] = o4.z; }
        if (e0 + 3 < n) { off[e0 + 3] = o4.w; cur[e0 + 3] = o4.w; }
    }
}

// ---------------------------------------------------------------------------
// Bin edges by destination: slot = atomic cursor bump, store source id.
// ---------------------------------------------------------------------------
__global__ void bin_kernel(const int* __restrict__ rate_src, const int* __restrict__ rate_dst,
                           const int* __restrict__ rev_src,  const int* __restrict__ rev_dst) {
    int i = blockIdx.x * blockDim.x + threadIdx.x;
    if (i < NEDGE) {
        int p = atomicAdd(&g_cur_item[__ldg(rate_dst + i)], 1);
        g_esrc_item[p] = __ldg(rate_src + i);
        int q = atomicAdd(&g_cur_user[__ldg(rev_dst + i)], 1);
        g_esrc_user[q] = __ldg(rev_src + i);
    }
}

// ---------------------------------------------------------------------------
// Gather-based segment mean over fp16 rows: 16 threads per dst node, each
// owns 4 halves (8B) of the 128B row. Accumulate fp32, write fp32 mean.
// ---------------------------------------------------------------------------
__global__ void agg_kernel(const __half* __restrict__ feat, const int* __restrict__ esrc,
                           const int* __restrict__ off, const int* __restrict__ deg,
                           float* __restrict__ mean) {
    int t = blockIdx.x * blockDim.x + threadIdx.x;
    int g = t >> 4;          // node id (grid sized exactly: nnode*16 threads)
    int lane = t & 15;
    int dgc = __ldg(deg + g);
    int start = __ldg(off + g);
    float4 acc = make_float4(0.f, 0.f, 0.f, 0.f);
    #pragma unroll 4
    for (int j = 0; j < dgc; j++) {
        int s = __ldg(esrc + start + j);
        uint2 p = *reinterpret_cast<const uint2*>(feat + (size_t)s * D + lane * 4);
        __half2 h0 = *reinterpret_cast<__half2*>(&p.x);
        __half2 h1 = *reinterpret_cast<__half2*>(&p.y);
        float2 f0 = __half22float2(h0);
        float2 f1 = __half22float2(h1);
        acc.x += f0.x; acc.y += f0.y; acc.z += f1.x; acc.w += f1.y;
    }
    float inv = (dgc > 0) ? 1.f / (float)dgc : 0.f;
    acc.x *= inv; acc.y *= inv; acc.z *= inv; acc.w *= inv;
    *reinterpret_cast<float4*>(mean + (size_t)g * D + lane * 4) = acc;
}

// ---------------------------------------------------------------------------
// Fused dual GEMM finalize:
//   out = feat @ W_loop + mean @ W_et + (deg>0 ? b_et : 0) + h_bias
// 64-row tile, 4x4 register blocking, two accumulate phases over shared tiles.
// ---------------------------------------------------------------------------
__global__ void final_kernel(const float* __restrict__ A0, const float* __restrict__ W0,
                             const float* __restrict__ A1, const float* __restrict__ W1,
                             const float* __restrict__ bet, const float* __restrict__ hb,
                             const int* __restrict__ deg, float* __restrict__ out, int N) {
    __shared__ float As[64][68];
    __shared__ float Ws[64][68];
    __shared__ float bias_h[64];
    __shared__ float bias_e[64];
    const int tid = threadIdx.x;
    const int tx = tid & 15, ty = tid >> 4;
    const int row0 = blockIdx.x * 64;
    const int rb = ty * 4;

    if (tid < 64) bias_h[tid] = hb[tid];
    else if (tid < 128) bias_e[tid - 64] = bet[tid - 64];

    float4 acc[4];
    #pragma unroll
    for (int i = 0; i < 4; i++) acc[i] = make_float4(0.f, 0.f, 0.f, 0.f);

    #pragma unroll
    for (int phase = 0; phase < 2; phase++) {
        const float* A = phase ? A1 : A0;
        const float* W = phase ? W1 : W0;
        __syncthreads();   // protect shared reuse from previous phase
        #pragma unroll
        for (int i = tid; i < 1024; i += 256) {
            int k = i >> 4, c4 = (i & 15) << 2;
            float4 w = *reinterpret_cast<const float4*>(W + k * 64 + c4);
            *reinterpret_cast<float4*>(&Ws[k][c4]) = w;
        }
        #pragma unroll
        for (int i = tid; i < 1024; i += 256) {
            int r = i >> 4, k4 = (i & 15) << 2;
            int gr = row0 + r;
            float4 a = (gr < N) ? *reinterpret_cast<const float4*>(A + (size_t)gr * D + k4)
                                : make_float4(0.f, 0.f, 0.f, 0.f);
            *reinterpret_cast<float4*>(&As[r][k4]) = a;
        }
        __syncthreads();
        #pragma unroll
        for (int k = 0; k < 64; k++) {
            float4 wv = *reinterpret_cast<const float4*>(&Ws[k][tx * 4]);
            float a0 = As[rb + 0][k], a1 = As[rb + 1][k], a2 = As[rb + 2][k], a3 = As[rb + 3][k];
            acc[0].x += a0 * wv.x; acc[0].y += a0 * wv.y; acc[0].z += a0 * wv.z; acc[0].w += a0 * wv.w;
            acc[1].x += a1 * wv.x; acc[1].y += a1 * wv.y; acc[1].z += a1 * wv.z; acc[1].w += a1 * wv.w;
            acc[2].x += a2 * wv.x; acc[2].y += a2 * wv.y; acc[2].z += a2 * wv.z; acc[2].w += a2 * wv.w;
            acc[3].x += a3 * wv.x; acc[3].y += a3 * wv.y; acc[3].z += a3 * wv.z; acc[3].w += a3 * wv.w;
        }
    }

    #pragma unroll
    for (int i = 0; i < 4; i++) {
        int gr = row0 + rb + i;
        if (gr < N) {
            float m = (__ldg(deg + gr) > 0) ? 1.f : 0.f;
            float4 r = acc[i];
            r.x += bias_h[tx * 4 + 0] + m * bias_e[tx * 4 + 0];
            r.y += bias_h[tx * 4 + 1] + m * bias_e[tx * 4 + 1];
            r.z += bias_h[tx * 4 + 2] + m * bias_e[tx * 4 + 2];
            r.w += bias_h[tx * 4 + 3] + m * bias_e[tx * 4 + 3];
            *reinterpret_cast<float4*>(out + (size_t)gr * D + tx * 4) = r;
        }
    }
}

extern "C" void kernel_launch(void* const* d_in, const int* in_sizes, int n_in,
                              void* d_out, int out_size) {
    const float* user_feat = (const float*)d_in[0];
    const float* item_feat = (const float*)d_in[1];
    const int*   rate_src  = (const int*)d_in[2];
    const int*   rate_dst  = (const int*)d_in[3];
    const int*   rev_src   = (const int*)d_in[4];
    const int*   rev_dst   = (const int*)d_in[5];
    const float* W_rate    = (const float*)d_in[6];
    const float* b_rate    = (const float*)d_in[7];
    const float* W_rev     = (const float*)d_in[8];
    const float* b_rev     = (const float*)d_in[9];
    const float* W_loop    = (const float*)d_in[10];
    const float* h_bias    = (const float*)d_in[11];

    float* out      = (float*)d_out;
    float* out_user = out;
    float* out_item = out + (size_t)NUSER * D;

    int *deg_item, *deg_user, *esrc_item, *esrc_user, *off_item, *off_user;
    float *mean_item, *mean_user;
    __half *uf_h, *if_h;
    cudaGetSymbolAddress((void**)&deg_item, g_deg_item);
    cudaGetSymbolAddress((void**)&deg_user, g_deg_user);
    cudaGetSymbolAddress((void**)&off_item, g_off_item);
    cudaGetSymbolAddress((void**)&off_user, g_off_user);
    cudaGetSymbolAddress((void**)&esrc_item, g_esrc_item);
    cudaGetSymbolAddress((void**)&esrc_user, g_esrc_user);
    cudaGetSymbolAddress((void**)&mean_item, g_mean_item);
    cudaGetSymbolAddress((void**)&mean_user, g_mean_user);
    cudaGetSymbolAddress((void**)&uf_h, g_uf_h);
    cudaGetSymbolAddress((void**)&if_h, g_if_h);

    init_kernel<<<(NUSER + 255) / 256, 256>>>();
    conv_kernel<<<(2 * NUSER * D / 4 + 255) / 256, 256>>>(user_feat, item_feat);
    hist_kernel<<<(NEDGE + 255) / 256, 256>>>(rate_dst, rev_dst);

    scan1_kernel<<<2 * NTILE, 256>>>();
    scan2_kernel<<<1, 64>>>();
    scan3_kernel<<<2 * NTILE, 256>>>();

    bin_kernel<<<(NEDGE + 255) / 256, 256>>>(rate_src, rate_dst, rev_src, rev_dst);

    // item side aggregates USER features; user side aggregates ITEM features.
    agg_kernel<<<NITEM * 16 / 256, 256>>>(uf_h, esrc_item, off_item, deg_item, mean_item);
    agg_kernel<<<NUSER * 16 / 256, 256>>>(if_h, esrc_user, off_user, deg_user, mean_user);

    final_kernel<<<(NUSER + 63) / 64, 256>>>(user_feat, W_loop, mean_user, W_rev,
                                             b_rev, h_bias, deg_user, out_user, NUSER);
    final_kernel<<<(NITEM + 63) / 64, 256>>>(item_feat, W_loop, mean_item, W_rate,
                                             b_rate, h_bias, deg_item, out_item, NITEM);
}

// round 7
// speedup vs baseline: 1.3760x; 1.0222x over previous
#include <cuda_runtime.h>
#include <cuda_fp16.h>
#include <cstdint>

#define NUSER 50000
#define NITEM 50000
#define NEDGE 1600000
#define D 64

#define TILE 1024
#define NTILE ((NUSER + TILE - 1) / TILE)   // 49 tiles per side

// ---- Scratch (device globals; allocation is forbidden) ----
__device__ __align__(16) int g_deg_item[NITEM];
__device__ __align__(16) int g_deg_user[NUSER];
__device__ __align__(16) int g_off_item[NITEM];
__device__ __align__(16) int g_off_user[NUSER];
__device__ int g_tsum[2][NTILE];          // per-tile sums (0=item, 1=user)
__device__ int g_tbase[2][NTILE];         // exclusive tile bases
__device__ int g_rank_item[NEDGE];        // rank of edge within its item bucket
__device__ int g_rank_user[NEDGE];        // rank of edge within its user bucket
__device__ int g_esrc_item[NEDGE];        // user ids, grouped by dst item
__device__ int g_esrc_user[NEDGE];        // item ids, grouped by dst user
__device__ __half g_uf_h[NUSER * D];      // user_feat in fp16 (gather table)
__device__ __half g_if_h[NITEM * D];      // item_feat in fp16 (gather table)
__device__ float g_mean_item[NITEM * D];  // mean of user_feat over in-edges
__device__ float g_mean_user[NUSER * D];  // mean of item_feat over in-edges

// ---------------------------------------------------------------------------
// Zero the degree counters.
// ---------------------------------------------------------------------------
__global__ void init_kernel() {
    int i = blockIdx.x * blockDim.x + threadIdx.x;
    if (i < NITEM) g_deg_item[i] = 0;
    if (i < NUSER) g_deg_user[i] = 0;
}

// ---------------------------------------------------------------------------
// Convert both fp32 feature tables to fp16 gather tables (float4 -> 4 halves).
// ---------------------------------------------------------------------------
__global__ void conv_kernel(const float* __restrict__ user_feat,
                            const float* __restrict__ item_feat) {
    const int n4 = NUSER * D / 4;          // 800000 per side
    int i = blockIdx.x * blockDim.x + threadIdx.x;
    if (i < n4) {
        float4 v = *reinterpret_cast<const float4*>(user_feat + (size_t)i * 4);
        __half2 lo = __floats2half2_rn(v.x, v.y);
        __half2 hi = __floats2half2_rn(v.z, v.w);
        uint2 p = make_uint2(*reinterpret_cast<uint32_t*>(&lo),
                             *reinterpret_cast<uint32_t*>(&hi));
        *reinterpret_cast<uint2*>(g_uf_h + (size_t)i * 4) = p;
    } else if (i < 2 * n4) {
        int j = i - n4;
        float4 v = *reinterpret_cast<const float4*>(item_feat + (size_t)j * 4);
        __half2 lo = __floats2half2_rn(v.x, v.y);
        __half2 hi = __floats2half2_rn(v.z, v.w);
        uint2 p = make_uint2(*reinterpret_cast<uint32_t*>(&lo),
                             *reinterpret_cast<uint32_t*>(&hi));
        *reinterpret_cast<uint2*>(g_if_h + (size_t)j * 4) = p;
    }
}

// ---------------------------------------------------------------------------
// Degree histogram for both edge types; the atomic's return value is the
// edge's rank within its destination bucket (stored coalesced for bin).
// ---------------------------------------------------------------------------
__global__ void hist_kernel(const int* __restrict__ rate_dst,
                            const int* __restrict__ rev_dst) {
    int i = blockIdx.x * blockDim.x + threadIdx.x;
    if (i < NEDGE) {
        g_rank_item[i] = atomicAdd(&g_deg_item[__ldg(rate_dst + i)], 1);
        g_rank_user[i] = atomicAdd(&g_deg_user[__ldg(rev_dst + i)], 1);
    }
}

// ---------------------------------------------------------------------------
// Scan step 1: per-tile reduction. Grid = 2*NTILE blocks, 256 threads.
// ---------------------------------------------------------------------------
__global__ void scan1_kernel() {
    int side = blockIdx.x / NTILE;
    int tile = blockIdx.x % NTILE;
    const int n = (side == 0) ? NITEM : NUSER;
    const int* __restrict__ deg = (side == 0) ? g_deg_item : g_deg_user;
    const int tid = threadIdx.x;
    const int e0 = tile * TILE + tid * 4;

    int s = 0;
    if (e0 + 3 < n) {
        int4 v = *reinterpret_cast<const int4*>(deg + e0);
        s = v.x + v.y + v.z + v.w;
    } else {
        for (int i = e0; i < min(e0 + 4, n); i++) s += __ldg(deg + i);
    }
    #pragma unroll
    for (int o = 16; o; o >>= 1) s += __shfl_down_sync(0xffffffffu, s, o);
    __shared__ int ws[8];
    if ((tid & 31) == 0) ws[tid >> 5] = s;
    __syncthreads();
    if (tid < 8) {
        int t = ws[tid];
        #pragma unroll
        for (int o = 4; o; o >>= 1) t += __shfl_down_sync(0xffu, t, o);
        if (tid == 0) g_tsum[side][tile] = t;
    }
}

// ---------------------------------------------------------------------------
// Scan step 2: exclusive scan of the NTILE tile sums, one warp per side.
// ---------------------------------------------------------------------------
__global__ void scan2_kernel() {
    int side = threadIdx.x >> 5;     // 2 warps
    int lane = threadIdx.x & 31;
    if (side < 2) {
        int v0 = (lane < NTILE) ? g_tsum[side][lane] : 0;
        int v1 = (lane + 32 < NTILE) ? g_tsum[side][lane + 32] : 0;
        int s0 = v0, s1 = v1;
        #pragma unroll
        for (int o = 1; o < 32; o <<= 1) {
            int t = __shfl_up_sync(0xffffffffu, s0, o);
            if (lane >= o) s0 += t;
            int u = __shfl_up_sync(0xffffffffu, s1, o);
            if (lane >= o) s1 += u;
        }
        int tot0 = __shfl_sync(0xffffffffu, s0, 31);
        if (lane < NTILE) g_tbase[side][lane] = s0 - v0;
        if (lane + 32 < NTILE) g_tbase[side][lane + 32] = tot0 + s1 - v1;
    }
}

// ---------------------------------------------------------------------------
// Scan step 3: per-tile exclusive scan + tile base -> off. Coalesced.
// ---------------------------------------------------------------------------
__global__ void scan3_kernel() {
    int side = blockIdx.x / NTILE;
    int tile = blockIdx.x % NTILE;
    const int n = (side == 0) ? NITEM : NUSER;
    const int* __restrict__ deg = (side == 0) ? g_deg_item : g_deg_user;
    int* __restrict__ off = (side == 0) ? g_off_item : g_off_user;
    const int tid = threadIdx.x, lane = tid & 31, wid = tid >> 5;
    const int e0 = tile * TILE + tid * 4;

    int4 v = make_int4(0, 0, 0, 0);
    if (e0 + 3 < n) {
        v = *reinterpret_cast<const int4*>(deg + e0);
    } else {
        if (e0 + 0 < n) v.x = __ldg(deg + e0 + 0);
        if (e0 + 1 < n) v.y = __ldg(deg + e0 + 1);
        if (e0 + 2 < n) v.z = __ldg(deg + e0 + 2);
        if (e0 + 3 < n) v.w = __ldg(deg + e0 + 3);
    }
    int tsum = v.x + v.y + v.z + v.w;

    int p = tsum;
    #pragma unroll
    for (int o = 1; o < 32; o <<= 1) {
        int t = __shfl_up_sync(0xffffffffu, p, o);
        if (lane >= o) p += t;
    }
    __shared__ int ws[8];
    if (lane == 31) ws[wid] = p;
    __syncthreads();
    if (tid < 8) {
        int t = ws[tid];
        #pragma unroll
        for (int o = 1; o < 8; o <<= 1) {
            int u = __shfl_up_sync(0xffu, t, o);
            if (tid >= o) t += u;
        }
        ws[tid] = t;
    }
    __syncthreads();
    int excl = (wid ? ws[wid - 1] : 0) + p - tsum + g_tbase[side][tile];

    int4 o4;
    o4.x = excl;
    o4.y = o4.x + v.x;
    o4.z = o4.y + v.y;
    o4.w = o4.z + v.z;
    if (e0 + 3 < n) {
        *reinterpret_cast<int4*>(off + e0) = o4;
    } else {
        if (e0 + 0 < n) off[e0 + 0] = o4.x;
        if (e0 + 1 < n) off[e0 + 1] = o4.y;
        if (e0 + 2 < n) off[e0 + 2] = o4.z;
        if (e0 + 3 < n) off[e0 + 3] = o4.w;
    }
}

// ---------------------------------------------------------------------------
// Bin edges by destination — NO atomics: slot = off[dst] + rank (rank was
// captured by hist's atomic). off table is 200KB, L2-resident scattered read.
// ---------------------------------------------------------------------------
__global__ void bin_kernel(const int* __restrict__ rate_src, const int* __restrict__ rate_dst,
                           const int* __restrict__ rev_src,  const int* __restrict__ rev_dst) {
    int i = blockIdx.x * blockDim.x + threadIdx.x;
    if (i < NEDGE) {
        int p = __ldg(&g_off_item[__ldg(rate_dst + i)]) + g_rank_item[i];
        g_esrc_item[p] = __ldg(rate_src + i);
        int q = __ldg(&g_off_user[__ldg(rev_dst + i)]) + g_rank_user[i];
        g_esrc_user[q] = __ldg(rev_src + i);
    }
}

// ---------------------------------------------------------------------------
// Gather-based segment mean over fp16 rows: 16 threads per dst node, each
// owns 4 halves (8B) of the 128B row. Accumulate fp32, write fp32 mean.
// ---------------------------------------------------------------------------
__global__ void agg_kernel(const __half* __restrict__ feat, const int* __restrict__ esrc,
                           const int* __restrict__ off, const int* __restrict__ deg,
                           float* __restrict__ mean) {
    int t = blockIdx.x * blockDim.x + threadIdx.x;
    int g = t >> 4;          // node id (grid sized exactly: nnode*16 threads)
    int lane = t & 15;
    int dgc = __ldg(deg + g);
    int start = __ldg(off + g);
    float4 acc = make_float4(0.f, 0.f, 0.f, 0.f);
    #pragma unroll 4
    for (int j = 0; j < dgc; j++) {
        int s = __ldg(esrc + start + j);
        uint2 p = *reinterpret_cast<const uint2*>(feat + (size_t)s * D + lane * 4);
        __half2 h0 = *reinterpret_cast<__half2*>(&p.x);
        __half2 h1 = *reinterpret_cast<__half2*>(&p.y);
        float2 f0 = __half22float2(h0);
        float2 f1 = __half22float2(h1);
        acc.x += f0.x; acc.y += f0.y; acc.z += f1.x; acc.w += f1.y;
    }
    float inv = (dgc > 0) ? 1.f / (float)dgc : 0.f;
    acc.x *= inv; acc.y *= inv; acc.z *= inv; acc.w *= inv;
    *reinterpret_cast<float4*>(mean + (size_t)g * D + lane * 4) = acc;
}

// ---------------------------------------------------------------------------
// Fused dual GEMM finalize:
//   out = feat @ W_loop + mean @ W_et + (deg>0 ? b_et : 0) + h_bias
// A tile stored TRANSPOSED in smem so the 4 row-values per k are one LDS.128.
// ---------------------------------------------------------------------------
__global__ void final_kernel(const float* __restrict__ A0, const float* __restrict__ W0,
                             const float* __restrict__ A1, const float* __restrict__ W1,
                             const float* __restrict__ bet, const float* __restrict__ hb,
                             const int* __restrict__ deg, float* __restrict__ out, int N) {
    __shared__ float At[64][68];    // At[k][row]
    __shared__ float Ws[64][68];    // Ws[k][col]
    __shared__ float bias_h[64];
    __shared__ float bias_e[64];
    const int tid = threadIdx.x;
    const int tx = tid & 15, ty = tid >> 4;
    const int row0 = blockIdx.x * 64;
    const int rb = ty * 4;

    if (tid < 64) bias_h[tid] = hb[tid];
    else if (tid < 128) bias_e[tid - 64] = bet[tid - 64];

    float4 acc[4];
    #pragma unroll
    for (int i = 0; i < 4; i++) acc[i] = make_float4(0.f, 0.f, 0.f, 0.f);

    #pragma unroll
    for (int phase = 0; phase < 2; phase++) {
        const float* A = phase ? A1 : A0;
        const float* W = phase ? W1 : W0;
        __syncthreads();   // protect shared reuse from previous phase
        #pragma unroll
        for (int i = tid; i < 1024; i += 256) {
            int k = i >> 4, c4 = (i & 15) << 2;
            float4 w = *reinterpret_cast<const float4*>(W + k * 64 + c4);
            *reinterpret_cast<float4*>(&Ws[k][c4]) = w;
        }
        #pragma unroll
        for (int i = tid; i < 1024; i += 256) {
            int r = i >> 4, k4 = (i & 15) << 2;
            int gr = row0 + r;
            float4 a = (gr < N) ? *reinterpret_cast<const float4*>(A + (size_t)gr * D + k4)
                                : make_float4(0.f, 0.f, 0.f, 0.f);
            At[k4 + 0][r] = a.x;
            At[k4 + 1][r] = a.y;
            At[k4 + 2][r] = a.z;
            At[k4 + 3][r] = a.w;
        }
        __syncthreads();
        #pragma unroll
        for (int k = 0; k < 64; k++) {
            float4 wv = *reinterpret_cast<const float4*>(&Ws[k][tx * 4]);
            float4 av = *reinterpret_cast<const float4*>(&At[k][rb]);
            acc[0].x += av.x * wv.x; acc[0].y += av.x * wv.y; acc[0].z += av.x * wv.z; acc[0].w += av.x * wv.w;
            acc[1].x += av.y * wv.x; acc[1].y += av.y * wv.y; acc[1].z += av.y * wv.z; acc[1].w += av.y * wv.w;
            acc[2].x += av.z * wv.x; acc[2].y += av.z * wv.y; acc[2].z += av.z * wv.z; acc[2].w += av.z * wv.w;
            acc[3].x += av.w * wv.x; acc[3].y += av.w * wv.y; acc[3].z += av.w * wv.z; acc[3].w += av.w * wv.w;
        }
    }

    #pragma unroll
    for (int i = 0; i < 4; i++) {
        int gr = row0 + rb + i;
        if (gr < N) {
            float m = (__ldg(deg + gr) > 0) ? 1.f : 0.f;
            float4 r = acc[i];
            r.x += bias_h[tx * 4 + 0] + m * bias_e[tx * 4 + 0];
            r.y += bias_h[tx * 4 + 1] + m * bias_e[tx * 4 + 1];
            r.z += bias_h[tx * 4 + 2] + m * bias_e[tx * 4 + 2];
            r.w += bias_h[tx * 4 + 3] + m * bias_e[tx * 4 + 3];
            *reinterpret_cast<float4*>(out + (size_t)gr * D + tx * 4) = r;
        }
    }
}

extern "C" void kernel_launch(void* const* d_in, const int* in_sizes, int n_in,
                              void* d_out, int out_size) {
    const float* user_feat = (const float*)d_in[0];
    const float* item_feat = (const float*)d_in[1];
    const int*   rate_src  = (const int*)d_in[2];
    const int*   rate_dst  = (const int*)d_in[3];
    const int*   rev_src   = (const int*)d_in[4];
    const int*   rev_dst   = (const int*)d_in[5];
    const float* W_rate    = (const float*)d_in[6];
    const float* b_rate    = (const float*)d_in[7];
    const float* W_rev     = (const float*)d_in[8];
    const float* b_rev     = (const float*)d_in[9];
    const float* W_loop    = (const float*)d_in[10];
    const float* h_bias    = (const float*)d_in[11];

    float* out      = (float*)d_out;
    float* out_user = out;
    float* out_item = out + (size_t)NUSER * D;

    int *deg_item, *deg_user, *esrc_item, *esrc_user, *off_item, *off_user;
    float *mean_item, *mean_user;
    __half *uf_h, *if_h;
    cudaGetSymbolAddress((void**)&deg_item, g_deg_item);
    cudaGetSymbolAddress((void**)&deg_user, g_deg_user);
    cudaGetSymbolAddress((void**)&off_item, g_off_item);
    cudaGetSymbolAddress((void**)&off_user, g_off_user);
    cudaGetSymbolAddress((void**)&esrc_item, g_esrc_item);
    cudaGetSymbolAddress((void**)&esrc_user, g_esrc_user);
    cudaGetSymbolAddress((void**)&mean_item, g_mean_item);
    cudaGetSymbolAddress((void**)&mean_user, g_mean_user);
    cudaGetSymbolAddress((void**)&uf_h, g_uf_h);
    cudaGetSymbolAddress((void**)&if_h, g_if_h);

    init_kernel<<<(NUSER + 255) / 256, 256>>>();
    conv_kernel<<<(2 * NUSER * D / 4 + 255) / 256, 256>>>(user_feat, item_feat);
    hist_kernel<<<(NEDGE + 255) / 256, 256>>>(rate_dst, rev_dst);

    scan1_kernel<<<2 * NTILE, 256>>>();
    scan2_kernel<<<1, 64>>>();
    scan3_kernel<<<2 * NTILE, 256>>>();

    bin_kernel<<<(NEDGE + 255) / 256, 256>>>(rate_src, rate_dst, rev_src, rev_dst);

    // item side aggregates USER features; user side aggregates ITEM features.
    agg_kernel<<<NITEM * 16 / 256, 256>>>(uf_h, esrc_item, off_item, deg_item, mean_item);
    agg_kernel<<<NUSER * 16 / 256, 256>>>(if_h, esrc_user, off_user, deg_user, mean_user);

    final_kernel<<<(NUSER + 63) / 64, 256>>>(user_feat, W_loop, mean_user, W_rev,
                                             b_rev, h_bias, deg_user, out_user, NUSER);
    final_kernel<<<(NITEM + 63) / 64, 256>>>(item_feat, W_loop, mean_item, W_rate,
                                             b_rate, h_bias, deg_item, out_item, NITEM);
}

// round 8
// speedup vs baseline: 1.3775x; 1.0011x over previous
#include <cuda_runtime.h>
#include <cuda_fp16.h>
#include <cstdint>

#define NUSER 50000
#define NITEM 50000
#define NEDGE 1600000
#define D 64

#define TILE 1024
#define NTILE ((NUSER + TILE - 1) / TILE)   // 49 tiles per side

// ---- Scratch (device globals; allocation is forbidden) ----
__device__ __align__(16) int g_deg_item[NITEM];
__device__ __align__(16) int g_deg_user[NUSER];
__device__ __align__(16) int g_off_item[NITEM];
__device__ __align__(16) int g_off_user[NUSER];
__device__ int g_tsum[2][NTILE];          // per-tile sums (0=item, 1=user)
__device__ int g_tbase[2][NTILE];         // exclusive tile bases
__device__ int g_rank_item[NEDGE];        // rank of edge within its item bucket
__device__ int g_rank_user[NEDGE];        // rank of edge within its user bucket
__device__ int g_esrc_item[NEDGE];        // user ids, grouped by dst item
__device__ int g_esrc_user[NEDGE];        // item ids, grouped by dst user
__device__ __half g_uf_h[NUSER * D];      // user_feat in fp16 (gather table)
__device__ __half g_if_h[NITEM * D];      // item_feat in fp16 (gather table)
__device__ float g_mean_item[NITEM * D];  // mean of user_feat over in-edges
__device__ float g_mean_user[NUSER * D];  // mean of item_feat over in-edges

// ---- f32x2 packed helpers ----
__device__ __forceinline__ void ffma2(unsigned long long& d,
                                      unsigned long long a, unsigned long long b) {
    asm("fma.rn.f32x2 %0, %1, %2, %0;" : "+l"(d) : "l"(a), "l"(b));
}
__device__ __forceinline__ unsigned long long pk2(float lo, float hi) {
    unsigned long long r;
    asm("mov.b64 %0, {%1, %2};" : "=l"(r) : "f"(lo), "f"(hi));
    return r;
}
__device__ __forceinline__ unsigned long long bcast2(float x) {
    unsigned long long r;
    asm("mov.b64 %0, {%1, %1};" : "=l"(r) : "f"(x));
    return r;
}
__device__ __forceinline__ void unpk(unsigned long long v, float& lo, float& hi) {
    asm("mov.b64 {%0, %1}, %2;" : "=f"(lo), "=f"(hi) : "l"(v));
}

// ---------------------------------------------------------------------------
// Zero the degree counters.
// ---------------------------------------------------------------------------
__global__ void init_kernel() {
    int i = blockIdx.x * blockDim.x + threadIdx.x;
    if (i < NITEM) g_deg_item[i] = 0;
    if (i < NUSER) g_deg_user[i] = 0;
}

// ---------------------------------------------------------------------------
// Convert both fp32 feature tables to fp16 gather tables (float4 -> 4 halves).
// ---------------------------------------------------------------------------
__global__ void conv_kernel(const float* __restrict__ user_feat,
                            const float* __restrict__ item_feat) {
    const int n4 = NUSER * D / 4;          // 800000 per side
    int i = blockIdx.x * blockDim.x + threadIdx.x;
    if (i < n4) {
        float4 v = *reinterpret_cast<const float4*>(user_feat + (size_t)i * 4);
        __half2 lo = __floats2half2_rn(v.x, v.y);
        __half2 hi = __floats2half2_rn(v.z, v.w);
        uint2 p = make_uint2(*reinterpret_cast<uint32_t*>(&lo),
                             *reinterpret_cast<uint32_t*>(&hi));
        *reinterpret_cast<uint2*>(g_uf_h + (size_t)i * 4) = p;
    } else if (i < 2 * n4) {
        int j = i - n4;
        float4 v = *reinterpret_cast<const float4*>(item_feat + (size_t)j * 4);
        __half2 lo = __floats2half2_rn(v.x, v.y);
        __half2 hi = __floats2half2_rn(v.z, v.w);
        uint2 p = make_uint2(*reinterpret_cast<uint32_t*>(&lo),
                             *reinterpret_cast<uint32_t*>(&hi));
        *reinterpret_cast<uint2*>(g_if_h + (size_t)j * 4) = p;
    }
}

// ---------------------------------------------------------------------------
// Degree histogram; the atomic's return value is the edge's in-bucket rank.
// ---------------------------------------------------------------------------
__global__ void hist_kernel(const int* __restrict__ rate_dst,
                            const int* __restrict__ rev_dst) {
    int i = blockIdx.x * blockDim.x + threadIdx.x;
    if (i < NEDGE) {
        g_rank_item[i] = atomicAdd(&g_deg_item[__ldg(rate_dst + i)], 1);
        g_rank_user[i] = atomicAdd(&g_deg_user[__ldg(rev_dst + i)], 1);
    }
}

// ---------------------------------------------------------------------------
// Scan step 1: per-tile reduction.
// ---------------------------------------------------------------------------
__global__ void scan1_kernel() {
    int side = blockIdx.x / NTILE;
    int tile = blockIdx.x % NTILE;
    const int n = (side == 0) ? NITEM : NUSER;
    const int* __restrict__ deg = (side == 0) ? g_deg_item : g_deg_user;
    const int tid = threadIdx.x;
    const int e0 = tile * TILE + tid * 4;

    int s = 0;
    if (e0 + 3 < n) {
        int4 v = *reinterpret_cast<const int4*>(deg + e0);
        s = v.x + v.y + v.z + v.w;
    } else {
        for (int i = e0; i < min(e0 + 4, n); i++) s += __ldg(deg + i);
    }
    #pragma unroll
    for (int o = 16; o; o >>= 1) s += __shfl_down_sync(0xffffffffu, s, o);
    __shared__ int ws[8];
    if ((tid & 31) == 0) ws[tid >> 5] = s;
    __syncthreads();
    if (tid < 8) {
        int t = ws[tid];
        #pragma unroll
        for (int o = 4; o; o >>= 1) t += __shfl_down_sync(0xffu, t, o);
        if (tid == 0) g_tsum[side][tile] = t;
    }
}

// ---------------------------------------------------------------------------
// Scan step 2: exclusive scan of tile sums, one warp per side.
// ---------------------------------------------------------------------------
__global__ void scan2_kernel() {
    int side = threadIdx.x >> 5;     // 2 warps
    int lane = threadIdx.x & 31;
    if (side < 2) {
        int v0 = (lane < NTILE) ? g_tsum[side][lane] : 0;
        int v1 = (lane + 32 < NTILE) ? g_tsum[side][lane + 32] : 0;
        int s0 = v0, s1 = v1;
        #pragma unroll
        for (int o = 1; o < 32; o <<= 1) {
            int t = __shfl_up_sync(0xffffffffu, s0, o);
            if (lane >= o) s0 += t;
            int u = __shfl_up_sync(0xffffffffu, s1, o);
            if (lane >= o) s1 += u;
        }
        int tot0 = __shfl_sync(0xffffffffu, s0, 31);
        if (lane < NTILE) g_tbase[side][lane] = s0 - v0;
        if (lane + 32 < NTILE) g_tbase[side][lane + 32] = tot0 + s1 - v1;
    }
}

// ---------------------------------------------------------------------------
// Scan step 3: per-tile exclusive scan + tile base -> off. Coalesced.
// ---------------------------------------------------------------------------
__global__ void scan3_kernel() {
    int side = blockIdx.x / NTILE;
    int tile = blockIdx.x % NTILE;
    const int n = (side == 0) ? NITEM : NUSER;
    const int* __restrict__ deg = (side == 0) ? g_deg_item : g_deg_user;
    int* __restrict__ off = (side == 0) ? g_off_item : g_off_user;
    const int tid = threadIdx.x, lane = tid & 31, wid = tid >> 5;
    const int e0 = tile * TILE + tid * 4;

    int4 v = make_int4(0, 0, 0, 0);
    if (e0 + 3 < n) {
        v = *reinterpret_cast<const int4*>(deg + e0);
    } else {
        if (e0 + 0 < n) v.x = __ldg(deg + e0 + 0);
        if (e0 + 1 < n) v.y = __ldg(deg + e0 + 1);
        if (e0 + 2 < n) v.z = __ldg(deg + e0 + 2);
        if (e0 + 3 < n) v.w = __ldg(deg + e0 + 3);
    }
    int tsum = v.x + v.y + v.z + v.w;

    int p = tsum;
    #pragma unroll
    for (int o = 1; o < 32; o <<= 1) {
        int t = __shfl_up_sync(0xffffffffu, p, o);
        if (lane >= o) p += t;
    }
    __shared__ int ws[8];
    if (lane == 31) ws[wid] = p;
    __syncthreads();
    if (tid < 8) {
        int t = ws[tid];
        #pragma unroll
        for (int o = 1; o < 8; o <<= 1) {
            int u = __shfl_up_sync(0xffu, t, o);
            if (tid >= o) t += u;
        }
        ws[tid] = t;
    }
    __syncthreads();
    int excl = (wid ? ws[wid - 1] : 0) + p - tsum + g_tbase[side][tile];

    int4 o4;
    o4.x = excl;
    o4.y = o4.x + v.x;
    o4.z = o4.y + v.y;
    o4.w = o4.z + v.z;
    if (e0 + 3 < n) {
        *reinterpret_cast<int4*>(off + e0) = o4;
    } else {
        if (e0 + 0 < n) off[e0 + 0] = o4.x;
        if (e0 + 1 < n) off[e0 + 1] = o4.y;
        if (e0 + 2 < n) off[e0 + 2] = o4.z;
        if (e0 + 3 < n) off[e0 + 3] = o4.w;
    }
}

// ---------------------------------------------------------------------------
// Bin edges by destination: slot = off[dst] + rank. No atomics.
// ---------------------------------------------------------------------------
__global__ void bin_kernel(const int* __restrict__ rate_src, const int* __restrict__ rate_dst,
                           const int* __restrict__ rev_src,  const int* __restrict__ rev_dst) {
    int i = blockIdx.x * blockDim.x + threadIdx.x;
    if (i < NEDGE) {
        int p = __ldg(&g_off_item[__ldg(rate_dst + i)]) + g_rank_item[i];
        g_esrc_item[p] = __ldg(rate_src + i);
        int q = __ldg(&g_off_user[__ldg(rev_dst + i)]) + g_rank_user[i];
        g_esrc_user[q] = __ldg(rev_src + i);
    }
}

// ---------------------------------------------------------------------------
// Gather-based segment mean over fp16 rows: 16 threads per dst node.
// ---------------------------------------------------------------------------
__global__ void agg_kernel(const __half* __restrict__ feat, const int* __restrict__ esrc,
                           const int* __restrict__ off, const int* __restrict__ deg,
                           float* __restrict__ mean) {
    int t = blockIdx.x * blockDim.x + threadIdx.x;
    int g = t >> 4;          // node id (grid sized exactly: nnode*16 threads)
    int lane = t & 15;
    int dgc = __ldg(deg + g);
    int start = __ldg(off + g);
    float4 acc = make_float4(0.f, 0.f, 0.f, 0.f);
    #pragma unroll 4
    for (int j = 0; j < dgc; j++) {
        int s = __ldg(esrc + start + j);
        uint2 p = *reinterpret_cast<const uint2*>(feat + (size_t)s * D + lane * 4);
        __half2 h0 = *reinterpret_cast<__half2*>(&p.x);
        __half2 h1 = *reinterpret_cast<__half2*>(&p.y);
        float2 f0 = __half22float2(h0);
        float2 f1 = __half22float2(h1);
        acc.x += f0.x; acc.y += f0.y; acc.z += f1.x; acc.w += f1.y;
    }
    float inv = (dgc > 0) ? 1.f / (float)dgc : 0.f;
    acc.x *= inv; acc.y *= inv; acc.z *= inv; acc.w *= inv;
    *reinterpret_cast<float4*>(mean + (size_t)g * D + lane * 4) = acc;
}

// ---------------------------------------------------------------------------
// Fused dual GEMM finalize with packed f32x2 FFMA:
//   out = feat @ W_loop + mean @ W_et + (deg>0 ? b_et : 0) + h_bias
// Same tiling/LDS pattern as r7 (transposed At, 2x LDS.128 per k); only the
// accumulate is packed: rows paired as f32x2, weights broadcast.
// acc[p][c] = ( row_{2p} col, row_{2p+1} col ) for c = tx*4 + c.
// ---------------------------------------------------------------------------
__global__ void final_kernel(const float* __restrict__ A0, const float* __restrict__ W0,
                             const float* __restrict__ A1, const float* __restrict__ W1,
                             const float* __restrict__ bet, const float* __restrict__ hb,
                             const int* __restrict__ deg, float* __restrict__ out, int N) {
    __shared__ float At[64][68];    // At[k][row]
    __shared__ float Ws[64][68];    // Ws[k][col]
    __shared__ float bias_h[64];
    __shared__ float bias_e[64];
    const int tid = threadIdx.x;
    const int tx = tid & 15, ty = tid >> 4;
    const int row0 = blockIdx.x * 64;
    const int rb = ty * 4;

    if (tid < 64) bias_h[tid] = hb[tid];
    else if (tid < 128) bias_e[tid - 64] = bet[tid - 64];

    unsigned long long acc[2][4];   // [row pair][col]
    #pragma unroll
    for (int p = 0; p < 2; p++)
        #pragma unroll
        for (int c = 0; c < 4; c++) acc[p][c] = 0ull;

    #pragma unroll
    for (int phase = 0; phase < 2; phase++) {
        const float* A = phase ? A1 : A0;
        const float* W = phase ? W1 : W0;
        __syncthreads();   // protect shared reuse from previous phase
        #pragma unroll
        for (int i = tid; i < 1024; i += 256) {
            int k = i >> 4, c4 = (i & 15) << 2;
            float4 w = *reinterpret_cast<const float4*>(W + k * 64 + c4);
            *reinterpret_cast<float4*>(&Ws[k][c4]) = w;
        }
        #pragma unroll
        for (int i = tid; i < 1024; i += 256) {
            int r = i >> 4, k4 = (i & 15) << 2;
            int gr = row0 + r;
            float4 a = (gr < N) ? *reinterpret_cast<const float4*>(A + (size_t)gr * D + k4)
                                : make_float4(0.f, 0.f, 0.f, 0.f);
            At[k4 + 0][r] = a.x;
            At[k4 + 1][r] = a.y;
            At[k4 + 2][r] = a.z;
            At[k4 + 3][r] = a.w;
        }
        __syncthreads();
        #pragma unroll
        for (int k = 0; k < 64; k++) {
            float4 wv = *reinterpret_cast<const float4*>(&Ws[k][tx * 4]);
            float4 av = *reinterpret_cast<const float4*>(&At[k][rb]);
            unsigned long long a01 = pk2(av.x, av.y);   // rows rb, rb+1
            unsigned long long a23 = pk2(av.z, av.w);   // rows rb+2, rb+3
            unsigned long long wx = bcast2(wv.x);
            unsigned long long wy = bcast2(wv.y);
            unsigned long long wz = bcast2(wv.z);
            unsigned long long ww = bcast2(wv.w);
            ffma2(acc[0][0], a01, wx); ffma2(acc[0][1], a01, wy);
            ffma2(acc[0][2], a01, wz); ffma2(acc[0][3], a01, ww);
            ffma2(acc[1][0], a23, wx); ffma2(acc[1][1], a23, wy);
            ffma2(acc[1][2], a23, wz); ffma2(acc[1][3], a23, ww);
        }
    }

    // Unpack: acc[p][c] = (row 2p value, row 2p+1 value) for column tx*4+c.
    float rv[4][4];
    #pragma unroll
    for (int p = 0; p < 2; p++)
        #pragma unroll
        for (int c = 0; c < 4; c++)
            unpk(acc[p][c], rv[2 * p][c], rv[2 * p + 1][c]);

    #pragma unroll
    for (int i = 0; i < 4; i++) {
        int gr = row0 + rb + i;
        if (gr < N) {
            float m = (__ldg(deg + gr) > 0) ? 1.f : 0.f;
            float4 r;
            r.x = rv[i][0] + bias_h[tx * 4 + 0] + m * bias_e[tx * 4 + 0];
            r.y = rv[i][1] + bias_h[tx * 4 + 1] + m * bias_e[tx * 4 + 1];
            r.z = rv[i][2] + bias_h[tx * 4 + 2] + m * bias_e[tx * 4 + 2];
            r.w = rv[i][3] + bias_h[tx * 4 + 3] + m * bias_e[tx * 4 + 3];
            *reinterpret_cast<float4*>(out + (size_t)gr * D + tx * 4) = r;
        }
    }
}

extern "C" void kernel_launch(void* const* d_in, const int* in_sizes, int n_in,
                              void* d_out, int out_size) {
    const float* user_feat = (const float*)d_in[0];
    const float* item_feat = (const float*)d_in[1];
    const int*   rate_src  = (const int*)d_in[2];
    const int*   rate_dst  = (const int*)d_in[3];
    const int*   rev_src   = (const int*)d_in[4];
    const int*   rev_dst   = (const int*)d_in[5];
    const float* W_rate    = (const float*)d_in[6];
    const float* b_rate    = (const float*)d_in[7];
    const float* W_rev     = (const float*)d_in[8];
    const float* b_rev     = (const float*)d_in[9];
    const float* W_loop    = (const float*)d_in[10];
    const float* h_bias    = (const float*)d_in[11];

    float* out      = (float*)d_out;
    float* out_user = out;
    float* out_item = out + (size_t)NUSER * D;

    int *deg_item, *deg_user, *esrc_item, *esrc_user, *off_item, *off_user;
    float *mean_item, *mean_user;
    __half *uf_h, *if_h;
    cudaGetSymbolAddress((void**)&deg_item, g_deg_item);
    cudaGetSymbolAddress((void**)&deg_user, g_deg_user);
    cudaGetSymbolAddress((void**)&off_item, g_off_item);
    cudaGetSymbolAddress((void**)&off_user, g_off_user);
    cudaGetSymbolAddress((void**)&esrc_item, g_esrc_item);
    cudaGetSymbolAddress((void**)&esrc_user, g_esrc_user);
    cudaGetSymbolAddress((void**)&mean_item, g_mean_item);
    cudaGetSymbolAddress((void**)&mean_user, g_mean_user);
    cudaGetSymbolAddress((void**)&uf_h, g_uf_h);
    cudaGetSymbolAddress((void**)&if_h, g_if_h);

    init_kernel<<<(NUSER + 255) / 256, 256>>>();
    conv_kernel<<<(2 * NUSER * D / 4 + 255) / 256, 256>>>(user_feat, item_feat);
    hist_kernel<<<(NEDGE + 255) / 256, 256>>>(rate_dst, rev_dst);

    scan1_kernel<<<2 * NTILE, 256>>>();
    scan2_kernel<<<1, 64>>>();
    scan3_kernel<<<2 * NTILE, 256>>>();

    bin_kernel<<<(NEDGE + 255) / 256, 256>>>(rate_src, rate_dst, rev_src, rev_dst);

    // item side aggregates USER features; user side aggregates ITEM features.
    agg_kernel<<<NITEM * 16 / 256, 256>>>(uf_h, esrc_item, off_item, deg_item, mean_item);
    agg_kernel<<<NUSER * 16 / 256, 256>>>(if_h, esrc_user, off_user, deg_user, mean_user);

    final_kernel<<<(NUSER + 63) / 64, 256>>>(user_feat, W_loop, mean_user, W_rev,
                                             b_rev, h_bias, deg_user, out_user, NUSER);
    final_kernel<<<(NITEM + 63) / 64, 256>>>(item_feat, W_loop, mean_item, W_rate,
                                             b_rate, h_bias, deg_item, out_item, NITEM);
}